// round 15
// baseline (speedup 1.0000x reference)
#include <cuda_runtime.h>
#include <cuda_fp16.h>
#include <math.h>

#define NN 100000
#define DD 128
#define AA 4096
#define SS 512
// exp(sim/TEMP) = exp2(sim * 10 * log2(e)) = exp2(sim * 14.4269504089f)

// Scratch (no device mallocs allowed)
__device__ __half g_xh[(size_t)NN * DD];   // normalized fp16 features, 25.6 MB
__device__ float  g_aloss[AA];
__device__ int    g_done = 0;              // ticket counter for last-block reduce

__device__ __forceinline__ float ex2_approx(float v) {
    float r;
    asm("ex2.approx.ftz.f32 %0, %1;" : "=f"(r) : "f"(v));
    return r;
}

__device__ __forceinline__ __half2 shfl_xor_h2(__half2 v, int o) {
    unsigned u = __shfl_xor_sync(0xFFFFFFFFu, *reinterpret_cast<unsigned*>(&v), o);
    return *reinterpret_cast<__half2*>(&u);
}

// ---------------------------------------------------------------------------
// Kernel 1: fused normalize + fp16 convert. FOUR rows per warp (MLP=4).
// __ldcs: x read exactly once -> evict-first, keep L2 warm for g_xh.
// ---------------------------------------------------------------------------
__global__ void norm_convert_kernel(const float* __restrict__ x) {
    int warp = (blockIdx.x * blockDim.x + threadIdx.x) >> 5;
    int lane = threadIdx.x & 31;
    int r0 = warp * 4;
    if (r0 >= NN) return;

    float4 v[4];
    bool has[4];
#pragma unroll
    for (int k = 0; k < 4; k++) {
        int r = r0 + k;
        has[k] = (r < NN);
        v[k] = has[k]
            ? __ldcs(reinterpret_cast<const float4*>(x + (size_t)r * DD) + lane)
            : make_float4(0.f, 0.f, 0.f, 0.f);
    }

    float s[4];
#pragma unroll
    for (int k = 0; k < 4; k++)
        s[k] = v[k].x * v[k].x + v[k].y * v[k].y + v[k].z * v[k].z + v[k].w * v[k].w;

#pragma unroll
    for (int o = 16; o; o >>= 1) {
#pragma unroll
        for (int k = 0; k < 4; k++)
            s[k] += __shfl_xor_sync(0xFFFFFFFFu, s[k], o);
    }

#pragma unroll
    for (int k = 0; k < 4; k++) {
        if (!has[k]) continue;
        float inv = rsqrtf(s[k]);
        __half2 h[2];
        h[0] = __floats2half2_rn(v[k].x * inv, v[k].y * inv);
        h[1] = __floats2half2_rn(v[k].z * inv, v[k].w * inv);
        reinterpret_cast<uint2*>(g_xh + (size_t)(r0 + k) * DD)[lane] =
            *reinterpret_cast<uint2*>(h);
    }
}

// ---------------------------------------------------------------------------
// Kernel 2: one block (8 warps) per anchor. Half-warp per sample (16 lanes x
// float4 = 256 B coalesced row). TWO chains per half-warp whose partial sums
// are PACKED into one half2 and reduced with a single 4-step shuffle chain
// (4 SHFL + 4 HADD2 per 2 samples -> half the MIO pressure). Depth-3 prefetch
// ring per chain keeps 6 LDGs in flight. Label match pre-resolved to a float
// flag at staging time.
// ---------------------------------------------------------------------------
__global__ __launch_bounds__(256) void loss_kernel(
    const int* __restrict__ y,
    const int* __restrict__ anchors,
    const int* __restrict__ sampled,
    float* __restrict__ out)
{
    __shared__ int2  s_iy[SS];               // (sample index, match-flag as float bits)
    __shared__ float s_num[16], s_den[16], s_cnt[16];
    __shared__ int   s_last;
    __shared__ float s_red[256];

    int a    = blockIdx.x;
    int tid  = threadIdx.x;
    int lane = tid & 31;
    int warp = tid >> 5;     // 0..7
    int hw   = lane >> 4;    // half-warp id (0/1)
    int hl   = lane & 15;    // lane within half-warp

    int ai = anchors[a];
    int ay = y[ai];

    // Stage sample indices + pre-resolved match flags (random 4B gathers
    // batched here with 256 threads of MLP, out of the hot loop).
    for (int i = tid; i < SS; i += 256) {
        int si = sampled[(size_t)a * SS + i];
        float flag = (y[si] == ay) ? 1.0f : 0.0f;
        s_iy[i] = make_int2(si, __float_as_int(flag));
    }

    // Anchor row: 8 fp16 per half-lane, kept as half2 (no conversion)
    __half2 ah[4];
    {
        float4 ar = reinterpret_cast<const float4*>(g_xh + (size_t)ai * DD)[hl];
        const __half2* p = reinterpret_cast<const __half2*>(&ar);
#pragma unroll
        for (int j = 0; j < 4; j++) ah[j] = p[j];
    }
    __syncthreads();

    const int offA = warp * 2 + hw;          // 0..15
    const int offB = offA + 16;              // 16..31
    float num = 0.0f, den = 0.0f, cnt = 0.0f;

    // Two chains, each with a depth-3 prefetch ring (6 LDGs in flight)
    float4 bufA[3], bufB[3];
    float  fA[3],   fB[3];
#pragma unroll
    for (int p = 0; p < 3; p++) {
        int2 ia = s_iy[p * 32 + offA];
        int2 ib = s_iy[p * 32 + offB];
        bufA[p] = reinterpret_cast<const float4*>(g_xh + (size_t)ia.x * DD)[hl];
        bufB[p] = reinterpret_cast<const float4*>(g_xh + (size_t)ib.x * DD)[hl];
        fA[p] = __int_as_float(ia.y);
        fB[p] = __int_as_float(ib.y);
    }

#pragma unroll
    for (int it = 0; it < 16; it++) {        // 16 iterations x 32 samples
        int slot = it % 3;
        float4 ca = bufA[slot]; float flagA = fA[slot];
        float4 cb = bufB[slot]; float flagB = fB[slot];
        if (it + 3 < 16) {
            int2 ia = s_iy[(it + 3) * 32 + offA];
            int2 ib = s_iy[(it + 3) * 32 + offB];
            bufA[slot] = reinterpret_cast<const float4*>(g_xh + (size_t)ia.x * DD)[hl];
            bufB[slot] = reinterpret_cast<const float4*>(g_xh + (size_t)ib.x * DD)[hl];
            fA[slot] = __int_as_float(ia.y);
            fB[slot] = __int_as_float(ib.y);
        }

        // Chain A dot (fp16x2, depth 4)
        const __half2* sa = reinterpret_cast<const __half2*>(&ca);
        __half2 accA = __hmul2(ah[0], sa[0]);
        accA = __hfma2(ah[1], sa[1], accA);
        accA = __hfma2(ah[2], sa[2], accA);
        accA = __hfma2(ah[3], sa[3], accA);

        // Chain B dot (independent)
        const __half2* sb = reinterpret_cast<const __half2*>(&cb);
        __half2 accB = __hmul2(ah[0], sb[0]);
        accB = __hfma2(ah[1], sb[1], accB);
        accB = __hfma2(ah[2], sb[2], accB);
        accB = __hfma2(ah[3], sb[3], accB);

        // Pack per-lane scalars of both chains into one half2: (sumA, sumB)
        __half2 d2 = __hadd2(__lows2half2(accA, accB), __highs2half2(accA, accB));

        // ONE 16-lane reduce for both chains (4 SHFL + 4 HADD2)
#pragma unroll
        for (int o = 8; o; o >>= 1) d2 = __hadd2(d2, shfl_xor_h2(d2, o));

        float2 df = __half22float2(d2);
        float eA = ex2_approx(df.x * 14.4269504089f);   // exp(simA * 10)
        float eB = ex2_approx(df.y * 14.4269504089f);
        den += eA + eB;
        num = fmaf(flagA, eA, num);
        num = fmaf(flagB, eB, num);
        cnt += flagA + flagB;
    }

    // Sums are uniform within the half-warp
    if (hl == 0) { s_num[offA] = num; s_den[offA] = den; s_cnt[offA] = cnt; }
    __syncthreads();

    if (tid == 0) {
        float nm = 0.0f, dn = 0.0f, c = 0.0f;
#pragma unroll
        for (int k = 0; k < 16; k++) { nm += s_num[k]; dn += s_den[k]; c += s_cnt[k]; }
        float loss = 0.0f;
        if (c > 0.0f) loss = (logf(dn) - logf(nm)) / c;  // -log(num/den)/cnt
        g_aloss[a] = loss;
        __threadfence();
        int t = atomicAdd(&g_done, 1);
        s_last = (t == AA - 1) ? 1 : 0;
    }
    __syncthreads();

    // Last block to finish: deterministic fixed-order reduction of g_aloss.
    if (s_last) {
        float s = 0.0f;
        for (int i = tid; i < AA; i += 256) s += g_aloss[i];
        s_red[tid] = s;
        __syncthreads();
        for (int o = 128; o; o >>= 1) {
            if (tid < o) s_red[tid] += s_red[tid + o];
            __syncthreads();
        }
        if (tid == 0) {
            out[0] = s_red[0];
            g_done = 0;                      // reset for next graph replay
        }
    }
}

extern "C" void kernel_launch(void* const* d_in, const int* in_sizes, int n_in,
                              void* d_out, int out_size) {
    const float* x       = (const float*)d_in[0];
    const int*   y       = (const int*)  d_in[1];
    const int*   anchors = (const int*)  d_in[2];
    const int*   sampled = (const int*)  d_in[3];
    float*       out     = (float*)d_out;

    (void)in_sizes; (void)n_in; (void)out_size;

    // 4 rows per warp -> 32 rows per 256-thread block
    norm_convert_kernel<<<(NN + 31) / 32, 256>>>(x);
    loss_kernel<<<AA, 256>>>(y, anchors, sampled, out);
}

// round 17
// speedup vs baseline: 1.2325x; 1.2325x over previous
#include <cuda_runtime.h>
#include <cuda_fp16.h>
#include <math.h>

#define NN 100000
#define DD 128
#define AA 4096
#define SS 512
// exp(sim/TEMP) = exp2(sim * 10 * log2(e)) = exp2(sim * 14.4269504089f)

// Scratch (no device mallocs allowed)
__device__ __half g_xh[(size_t)NN * DD];   // normalized fp16 features, 25.6 MB
__device__ float  g_aloss[AA];
__device__ int    g_done = 0;              // ticket counter for last-block reduce

__device__ __forceinline__ float ex2_approx(float v) {
    float r;
    asm("ex2.approx.ftz.f32 %0, %1;" : "=f"(r) : "f"(v));
    return r;
}

// ---------------------------------------------------------------------------
// Kernel 1: fused normalize + fp16 convert. FOUR rows per warp (MLP=4).
// ---------------------------------------------------------------------------
__global__ void norm_convert_kernel(const float* __restrict__ x) {
    int warp = (blockIdx.x * blockDim.x + threadIdx.x) >> 5;
    int lane = threadIdx.x & 31;
    int r0 = warp * 4;
    if (r0 >= NN) return;

    float4 v[4];
    bool has[4];
#pragma unroll
    for (int k = 0; k < 4; k++) {
        int r = r0 + k;
        has[k] = (r < NN);
        v[k] = has[k]
            ? __ldcs(reinterpret_cast<const float4*>(x + (size_t)r * DD) + lane)
            : make_float4(0.f, 0.f, 0.f, 0.f);
    }

    float s[4];
#pragma unroll
    for (int k = 0; k < 4; k++)
        s[k] = v[k].x * v[k].x + v[k].y * v[k].y + v[k].z * v[k].z + v[k].w * v[k].w;

#pragma unroll
    for (int o = 16; o; o >>= 1) {
#pragma unroll
        for (int k = 0; k < 4; k++)
            s[k] += __shfl_xor_sync(0xFFFFFFFFu, s[k], o);
    }

#pragma unroll
    for (int k = 0; k < 4; k++) {
        if (!has[k]) continue;
        float inv = rsqrtf(s[k]);
        __half2 h[2];
        h[0] = __floats2half2_rn(v[k].x * inv, v[k].y * inv);
        h[1] = __floats2half2_rn(v[k].z * inv, v[k].w * inv);
        reinterpret_cast<uint2*>(g_xh + (size_t)(r0 + k) * DD)[lane] =
            *reinterpret_cast<uint2*>(h);
    }
}

// ---------------------------------------------------------------------------
// Kernel 2: TENSOR-CORE formulation. One block (4 warps, 128 thr) per anchor.
// Each warp handles 128 samples as 8 tiles of 16. Per tile: cp.async-stage
// 16 gathered rows (256 B each) into smem, ldmatrix.x4 A-fragments, 8x
// mma.m16n8k16 (fp16 in, fp32 accum) against a B-fragment holding the anchor
// broadcast across N. Sims appear in fp32 C-fragments -> NO cross-lane
// shuffle reduce at all. 2-tile-deep cp.async pipeline hides gather latency.
// ---------------------------------------------------------------------------
#define TILE_STRIDE 272                  // bytes/row: 16B-aligned, ldmatrix conflict-free
#define TILE_BYTES  (16 * TILE_STRIDE)   // 4352 B per 16-sample tile

__global__ __launch_bounds__(128) void loss_kernel(
    const int* __restrict__ y,
    const int* __restrict__ anchors,
    const int* __restrict__ sampled,
    float* __restrict__ out)
{
    __shared__ int2  s_iy[SS];                        // (sample idx, match flag bits)
    __shared__ __align__(16) char s_tiles[4][2][TILE_BYTES];  // 34 KB
    __shared__ float s_num[4], s_den[4], s_cnt[4];
    __shared__ int   s_last;
    __shared__ float s_red[128];

    int a    = blockIdx.x;
    int tid  = threadIdx.x;
    int lane = tid & 31;
    int warp = tid >> 5;     // 0..3

    int ai = anchors[a];
    int ay = y[ai];

    // Stage sample indices + pre-resolved match flags (batched gathers).
    for (int i = tid; i < SS; i += 128) {
        int si = sampled[(size_t)a * SS + i];
        float flag = (y[si] == ay) ? 1.0f : 0.0f;
        s_iy[i] = make_int2(si, __float_as_int(flag));
    }

    // B fragments from the anchor row (broadcast over all 8 N columns, so only
    // the K mapping matters): reg0 = {a[k*16+2t], a[k*16+2t+1]},
    // reg1 = {a[k*16+2t+8], a[k*16+2t+9]}, t = lane%4.
    unsigned bfrag[8][2];
    {
        int t = lane & 3;
        const __half* arow = g_xh + (size_t)ai * DD;
#pragma unroll
        for (int k = 0; k < 8; k++) {
            bfrag[k][0] = *reinterpret_cast<const unsigned*>(arow + k * 16 + 2 * t);
            bfrag[k][1] = *reinterpret_cast<const unsigned*>(arow + k * 16 + 2 * t + 8);
        }
    }
    __syncthreads();

    unsigned buf_base[2];
    buf_base[0] = (unsigned)__cvta_generic_to_shared(&s_tiles[warp][0][0]);
    buf_base[1] = (unsigned)__cvta_generic_to_shared(&s_tiles[warp][1][0]);

    const int warp_base = warp * 128;    // 128 samples per warp
    // ldmatrix lane -> (row, k-half) address offset:
    // matrices ordered (r0-7,k0-7),(r8-15,k0-7),(r0-7,k8-15),(r8-15,k8-15)
    const int R      = (lane & 7) | (lane & 8);
    const int ld_off = R * TILE_STRIDE + ((lane >> 4) & 1) * 16;

    // Stage one 16-sample tile: 16 rows x 256 B via 8 x cp.async(16B)/lane.
    auto stage = [&](int tile) {
        int seg = lane & 15;
        int rbase = lane >> 4;
#pragma unroll
        for (int j = 0; j < 8; j++) {
            int row = 2 * j + rbase;
            int2 iy = s_iy[warp_base + tile * 16 + row];
            const __half* src = g_xh + (size_t)iy.x * DD + seg * 8;
            unsigned dst = buf_base[tile & 1] + row * TILE_STRIDE + seg * 16;
            asm volatile("cp.async.cg.shared.global [%0], [%1], 16;"
                         :: "r"(dst), "l"(src));
        }
    };

    stage(0); asm volatile("cp.async.commit_group;" ::: "memory");
    stage(1); asm volatile("cp.async.commit_group;" ::: "memory");

    float num = 0.0f, den = 0.0f, cnt = 0.0f;
    const int t4  = lane & 3;
    const int gid = lane >> 2;

#pragma unroll
    for (int t = 0; t < 8; t++) {
        asm volatile("cp.async.wait_group 1;" ::: "memory");
        __syncwarp();

        float c0 = 0.f, c1 = 0.f, c2 = 0.f, c3 = 0.f;
        unsigned abase = buf_base[t & 1] + ld_off;
#pragma unroll
        for (int k = 0; k < 8; k++) {
            unsigned a0, a1, a2, a3;
            asm volatile("ldmatrix.sync.aligned.m8n8.x4.shared.b16 {%0,%1,%2,%3}, [%4];"
                         : "=r"(a0), "=r"(a1), "=r"(a2), "=r"(a3)
                         : "r"(abase + k * 32));
            asm volatile("mma.sync.aligned.m16n8k16.row.col.f32.f16.f16.f32 "
                         "{%0,%1,%2,%3}, {%4,%5,%6,%7}, {%8,%9}, {%0,%1,%2,%3};"
                         : "+f"(c0), "+f"(c1), "+f"(c2), "+f"(c3)
                         : "r"(a0), "r"(a1), "r"(a2), "r"(a3),
                           "r"(bfrag[k][0]), "r"(bfrag[k][1]));
        }

        // Prefetch tile t+2 into the buffer we just consumed (ldmatrix done).
        if (t + 2 < 8) stage(t + 2);
        asm volatile("cp.async.commit_group;" ::: "memory");  // empty group OK

        // C fragment: c0 = sim[row gid], c2 = sim[row gid+8] at N-col 0
        // (lanes with lane%4 == 0 hold column 0).
        if (t4 == 0) {
            int s0 = warp_base + t * 16 + gid;
            float f0 = __int_as_float(s_iy[s0].y);
            float f1 = __int_as_float(s_iy[s0 + 8].y);
            float e0 = ex2_approx(c0 * 14.4269504089f);   // exp(sim*10)
            float e1 = ex2_approx(c2 * 14.4269504089f);
            den += e0 + e1;
            num = fmaf(f0, e0, num);
            num = fmaf(f1, e1, num);
            cnt += f0 + f1;
        }
    }

    // Warp reduce (only lanes%4==0 hold nonzero partials)
#pragma unroll
    for (int o = 4; o <= 16; o <<= 1) {
        num += __shfl_xor_sync(0xFFFFFFFFu, num, o);
        den += __shfl_xor_sync(0xFFFFFFFFu, den, o);
        cnt += __shfl_xor_sync(0xFFFFFFFFu, cnt, o);
    }
    if (lane == 0) { s_num[warp] = num; s_den[warp] = den; s_cnt[warp] = cnt; }
    __syncthreads();

    if (tid == 0) {
        float nm = 0.f, dn = 0.f, c = 0.f;
#pragma unroll
        for (int w = 0; w < 4; w++) { nm += s_num[w]; dn += s_den[w]; c += s_cnt[w]; }
        float loss = 0.0f;
        if (c > 0.0f) loss = (logf(dn) - logf(nm)) / c;  // -log(num/den)/cnt
        g_aloss[a] = loss;
        __threadfence();
        int tkt = atomicAdd(&g_done, 1);
        s_last = (tkt == AA - 1) ? 1 : 0;
    }
    __syncthreads();

    // Last block to finish: deterministic fixed-order reduction of g_aloss.
    if (s_last) {
        float s = 0.0f;
        for (int i = tid; i < AA; i += 128) s += g_aloss[i];
        s_red[tid] = s;
        __syncthreads();
        for (int o = 64; o; o >>= 1) {
            if (tid < o) s_red[tid] += s_red[tid + o];
            __syncthreads();
        }
        if (tid == 0) {
            out[0] = s_red[0];
            g_done = 0;                      // reset for next graph replay
        }
    }
}

extern "C" void kernel_launch(void* const* d_in, const int* in_sizes, int n_in,
                              void* d_out, int out_size) {
    const float* x       = (const float*)d_in[0];
    const int*   y       = (const int*)  d_in[1];
    const int*   anchors = (const int*)  d_in[2];
    const int*   sampled = (const int*)  d_in[3];
    float*       out     = (float*)d_out;

    (void)in_sizes; (void)n_in; (void)out_size;

    // 4 rows per warp -> 32 rows per 256-thread block
    norm_convert_kernel<<<(NN + 31) / 32, 256>>>(x);
    loss_kernel<<<AA, 128>>>(y, anchors, sampled, out);
}